// round 15
// baseline (speedup 1.0000x reference)
#include <cuda_runtime.h>
#include <cuda_fp16.h>
#include <stdint.h>
#include <math.h>

#define THREADS  256
#define TILE     64
#define TPG      4      // tiles per CTA -> 256 rows
#define GPB      8      // CTAs per batch per mlp
#define LDIM     2048
#define NBATCH   128
#define RSTRIDE_B 272   // bytes per fp16 row (136 elems) -> conflict-free ldmatrix
#define RSTRIDE_W 68    // u32 words per row

typedef unsigned int u32;

// ---------------- PTX helpers ----------------
__device__ __forceinline__ u32 smem_u32(const void* p) {
    u32 a;
    asm("{ .reg .u64 t; cvta.to.shared.u64 t, %1; cvt.u32.u64 %0, t; }" : "=r"(a) : "l"(p));
    return a;
}
__device__ __forceinline__ void ldsm_x4(u32* r, u32 addr) {
    asm volatile("ldmatrix.sync.aligned.m8n8.x4.shared.b16 {%0,%1,%2,%3}, [%4];"
        : "=r"(r[0]), "=r"(r[1]), "=r"(r[2]), "=r"(r[3]) : "r"(addr));
}
__device__ __forceinline__ void ldsm_x4t(u32* r, u32 addr) {
    asm volatile("ldmatrix.sync.aligned.m8n8.x4.trans.shared.b16 {%0,%1,%2,%3}, [%4];"
        : "=r"(r[0]), "=r"(r[1]), "=r"(r[2]), "=r"(r[3]) : "r"(addr));
}
__device__ __forceinline__ void mma16816(float* d, const u32* a, u32 b0, u32 b1) {
    asm volatile("mma.sync.aligned.m16n8k16.row.col.f32.f16.f16.f32 "
        "{%0,%1,%2,%3}, {%4,%5,%6,%7}, {%8,%9}, {%0,%1,%2,%3};"
        : "+f"(d[0]), "+f"(d[1]), "+f"(d[2]), "+f"(d[3])
        : "r"(a[0]), "r"(a[1]), "r"(a[2]), "r"(a[3]), "r"(b0), "r"(b1));
}
// low half = fp16(a), high half = fp16(b); lw = fp16 residuals
__device__ __forceinline__ void split_pack_h(float a, float b, u32& hw, u32& lw) {
    u32 h;
    asm("cvt.rn.f16x2.f32 %0, %1, %2;" : "=r"(h) : "f"(b), "f"(a));
    __half2 hv = *reinterpret_cast<__half2*>(&h);
    float2 f = __half22float2(hv);
    float ar = a - f.x, br = b - f.y;
    u32 l;
    asm("cvt.rn.f16x2.f32 %0, %1, %2;" : "=r"(l) : "f"(br), "f"(ar));
    hw = h; lw = l;
}
__device__ __forceinline__ u32 pack_h(float a, float b) {
    u32 h;
    asm("cvt.rn.f16x2.f32 %0, %1, %2;" : "=r"(h) : "f"(b), "f"(a));
    return h;
}

// precomputed (emb x W1slot [+ b1 on slot 0]) tables: [mlp][slot*20+aa][col]
__device__ float g_tab[3 * 80 * 128];

__global__ void build_tables(const float* __restrict__ emb,
                             const float* __restrict__ W1l, const float* __restrict__ b1l,
                             const float* __restrict__ W1t, const float* __restrict__ b1t,
                             const float* __restrict__ W1p, const float* __restrict__ b1p,
                             float* __restrict__ out, int out_n) {
    int idx = blockIdx.x * blockDim.x + threadIdx.x;
    if (idx < out_n) out[idx] = 0.f;          // fold output zeroing here
    if (idx >= 3 * 80 * 128) return;
    int col  = idx & 127;
    int rest = idx >> 7;
    int mlp  = rest / 80;
    int s_aa = rest - mlp * 80;
    int slot = s_aa / 20;
    int aa   = s_aa - slot * 20;
    const float* W1 = (mlp == 0) ? W1l : (mlp == 1) ? W1t : W1p;
    const float* b1 = (mlp == 0) ? b1l : (mlp == 1) ? b1t : b1p;
    int geo  = (mlp == 2) ? 2 : 1;
    int nemb = mlp + 2;
    float s = 0.f;
    if (slot < nemb) {
        #pragma unroll
        for (int e = 0; e < 16; ++e)
            s += emb[aa * 16 + e] * W1[(size_t)(geo + slot * 16 + e) * 128 + col];
        if (slot == 0) s += b1[col];      // fold bias once
    }
    g_tab[idx] = s;
}

// smem layout (mlp-independent now)
#define OFF_W2H  0
#define OFF_XH   (OFF_W2H + 128 * RSTRIDE_B)
#define OFF_XL   (OFF_XH + TILE * RSTRIDE_B)
#define OFF_BIAS (OFF_XL + TILE * RSTRIDE_B)
#define SMEM_BYTES (OFF_BIAS + 2 * 512)        // ~69 KB -> 3 CTAs/SM

__global__ __launch_bounds__(THREADS, 3)
void mlp_energy_mma(const float* __restrict__ R,
                    const int*   __restrict__ seq,
                    const float* __restrict__ W1a, const float* __restrict__ W1b, const float* __restrict__ W1c,
                    const float* __restrict__ W2a, const float* __restrict__ W2b, const float* __restrict__ W2c,
                    const float* __restrict__ b2a, const float* __restrict__ b2b, const float* __restrict__ b2c,
                    const float* __restrict__ W3a, const float* __restrict__ W3b, const float* __restrict__ W3c,
                    const float* __restrict__ b3a, const float* __restrict__ b3b, const float* __restrict__ b3c,
                    float* __restrict__ out)
{
    const int mlp   = blockIdx.x >> 10;          // 0..2
    const int blk   = blockIdx.x & 1023;
    const int nemb  = mlp + 2;
    const int geo   = (mlp == 2) ? 2 : 1;
    const int nrows = LDIM - nemb + 1;

    const float* gW1 = (mlp == 0) ? W1a : (mlp == 1) ? W1b : W1c;
    const float* gW2 = (mlp == 0) ? W2a : (mlp == 1) ? W2b : W2c;
    const float* gb2 = (mlp == 0) ? b2a : (mlp == 1) ? b2b : b2c;
    const float* gW3 = (mlp == 0) ? W3a : (mlp == 1) ? W3b : W3c;
    const float* gb3 = (mlp == 0) ? b3a : (mlp == 1) ? b3b : b3c;

    extern __shared__ char smem[];
    float* b2s  = (float*)(smem + OFF_BIAS);
    float* W3s  = b2s + 128;

    const int tid  = threadIdx.x;
    const int wid  = tid >> 5;
    const int lane = tid & 31;
    const int batch = blk / GPB;
    const int group = blk % GPB;

    // ---- stage biases / W2 fp16 (K-major [K][128]) ----
    if (tid < 128) { b2s[tid] = gb2[tid]; W3s[tid] = gW3[tid]; }
    {
        u32* wh = (u32*)(smem + OFF_W2H);
        for (int idx = tid; idx < 128 * 64; idx += THREADS) {
            int k = idx >> 6, np = idx & 63;
            int n = 2 * np;
            float w0 = gW2[(size_t)k * 128 + n];
            float w1 = gW2[(size_t)k * 128 + n + 1];
            wh[k * RSTRIDE_W + np] = pack_h(w0, w1);
        }
    }
    __syncthreads();

    const float b3r = gb3[0];
    const float* Rb   = R   + (size_t)batch * LDIM * 3;
    const int*   seqb = seq + (size_t)batch * LDIM;
    const float4* tab4 = (const float4*)(g_tab + mlp * 10240);  // L2-hot table
    const int row_base = group * (TILE * TPG);

    // geo weight rows of W1 kept in registers (uniform per lane, L2-hot)
    float4 wg0 = *(const float4*)(gW1 + lane * 4);
    float4 wg1 = make_float4(0.f, 0.f, 0.f, 0.f);
    if (geo == 2) wg1 = *(const float4*)(gW1 + 128 + lane * 4);

    const u32 xh_b  = smem_u32(smem + OFF_XH);
    const u32 xl_b  = smem_u32(smem + OFF_XL);
    const u32 w2h_b = smem_u32(smem + OFF_W2H);

    // gemm mapping: 8 warps = 2 row-groups (32 rows) x 4 N-quarters (32 cols)
    const int rg = wid >> 2;
    const int cq = wid & 3;
    const int m0 = rg * 32;
    const u32 aoff0 = (u32)(m0 + (lane & 15)) * RSTRIDE_B + (u32)(lane >> 4) * 16;
    const u32 aoff1 = aoff0 + 16 * RSTRIDE_B;
    const int l8 = lane & 7, lg = lane >> 3;
    const u32 boff4 = (u32)(l8 + (lg & 1) * 8) * RSTRIDE_B
                    + (u32)(lg >> 1) * 16 + (u32)cq * 64;

    u32* hh = (u32*)(smem + OFF_XH);
    u32* hl = (u32*)(smem + OFF_XL);
    const int tq = lane >> 2;
    const int tc = 2 * (lane & 3);

    const int wrow0 = wid * 8;    // build: warp owns rows wrow0..wrow0+7

    float acc_e = 0.f;

    for (int tt = 0; tt < TPG; ++tt) {
        const int i0 = row_base + tt * TILE;
        __syncthreads();   // previous tile's gemm reads done

        // ======== build h1 (warp-per-row, broadcast table LDGs) ========
        {
            // lanes 0..7: geometry for row i0+wrow0+lane
            float geo0 = 0.f, geo1 = 0.f;
            {
                const int i = i0 + wrow0 + (lane & 7);
                if (lane < 8 && i < nrows) {
                    float p0x = Rb[i*3+0],     p0y = Rb[i*3+1],     p0z = Rb[i*3+2];
                    float p1x = Rb[(i+1)*3+0], p1y = Rb[(i+1)*3+1], p1z = Rb[(i+1)*3+2];
                    float d0x = p1x - p0x, d0y = p1y - p0y, d0z = p1z - p0z;
                    if (mlp == 0) {
                        geo0 = sqrtf(d0x*d0x + d0y*d0y + d0z*d0z);
                    } else if (mlp == 1) {
                        float p2x = Rb[(i+2)*3+0], p2y = Rb[(i+2)*3+1], p2z = Rb[(i+2)*3+2];
                        float d1x = p2x - p1x, d1y = p2y - p1y, d1z = p2z - p1z;
                        float dot01 = d0x*d1x + d0y*d1y + d0z*d1z;
                        float n0 = d0x*d0x + d0y*d0y + d0z*d0z;
                        float n1 = d1x*d1x + d1y*d1y + d1z*d1z;
                        float c  = -dot01 / (sqrtf(n0) * sqrtf(n1));
                        geo0 = fminf(1.f, fmaxf(-1.f, c));
                    } else {
                        float p2x = Rb[(i+2)*3+0], p2y = Rb[(i+2)*3+1], p2z = Rb[(i+2)*3+2];
                        float p3x = Rb[(i+3)*3+0], p3y = Rb[(i+3)*3+1], p3z = Rb[(i+3)*3+2];
                        float d1x = p2x - p1x, d1y = p2y - p1y, d1z = p2z - p1z;
                        float d2x = p3x - p2x, d2y = p3y - p2y, d2z = p3z - p2z;
                        float n1x = d0y*d1z - d0z*d1y;
                        float n1y = d0z*d1x - d0x*d1z;
                        float n1z = d0x*d1y - d0y*d1x;
                        float n2x = d1y*d2z - d1z*d2y;
                        float n2y = d1z*d2x - d1x*d2z;
                        float n2z = d1x*d2y - d1y*d2x;
                        float inv = rsqrtf(d1x*d1x + d1y*d1y + d1z*d1z);
                        float ux = d1x*inv, uy = d1y*inv, uz = d1z*inv;
                        float m1x = n1y*uz - n1z*uy;
                        float m1y = n1z*ux - n1x*uz;
                        float m1z = n1x*uy - n1y*ux;
                        float yv = m1x*n2x + m1y*n2y + m1z*n2z;
                        float xv = n1x*n2x + n1y*n2y + n1z*n2z;
                        float rinv = rsqrtf(xv*xv + yv*yv);
                        geo0 = yv * rinv;
                        geo1 = xv * rinv;
                    }
                }
            }
            // seq values for rows wrow0..wrow0+7 (+nemb-1)
            int sval;
            {
                int sidx = i0 + wrow0 + lane;
                sval = (sidx < LDIM) ? seqb[sidx] : 0;
            }

            #pragma unroll 4
            for (int r = 0; r < 8; ++r) {
                float g0 = __shfl_sync(0xffffffffu, geo0, r);
                float g1 = __shfl_sync(0xffffffffu, geo1, r);
                float4 s = make_float4(0.f, 0.f, 0.f, 0.f);
                for (int v = 0; v < nemb; ++v) {
                    int aa = __shfl_sync(0xffffffffu, sval, r + v);
                    float4 t = tab4[(v * 20 + aa) * 32 + lane];   // coalesced 512B row
                    s.x += t.x; s.y += t.y; s.z += t.z; s.w += t.w;
                }
                s.x += g0 * wg0.x; s.y += g0 * wg0.y; s.z += g0 * wg0.z; s.w += g0 * wg0.w;
                if (geo == 2) {
                    s.x += g1 * wg1.x; s.y += g1 * wg1.y; s.z += g1 * wg1.z; s.w += g1 * wg1.w;
                }
                u32 hw0, lw0, hw1, lw1;
                split_pack_h(fmaxf(s.x, 0.f), fmaxf(s.y, 0.f), hw0, lw0);
                split_pack_h(fmaxf(s.z, 0.f), fmaxf(s.w, 0.f), hw1, lw1);
                const int p = (wrow0 + r) * RSTRIDE_W + 2 * lane;
                *(uint2*)(hh + p) = make_uint2(hw0, hw1);
                *(uint2*)(hl + p) = make_uint2(lw0, lw1);
            }
        }
        __syncthreads();

        // ======== layer-2 GEMM: M=32 rows x N=32 cols per warp, 2-term fp16 ========
        float acc[4][2][4];
        #pragma unroll
        for (int nf = 0; nf < 4; ++nf)
            #pragma unroll
            for (int mf = 0; mf < 2; ++mf)
                #pragma unroll
                for (int q = 0; q < 4; ++q) acc[nf][mf][q] = 0.f;

        #pragma unroll 1
        for (int k = 0; k < 8; ++k) {
            u32 ah0[4], ah1[4], al0[4], al1[4];
            ldsm_x4(ah0, xh_b + aoff0 + k * 32);
            ldsm_x4(ah1, xh_b + aoff1 + k * 32);
            ldsm_x4(al0, xl_b + aoff0 + k * 32);
            ldsm_x4(al1, xl_b + aoff1 + k * 32);
            u32 bk = boff4 + (u32)k * 16 * RSTRIDE_B;
            #pragma unroll
            for (int p = 0; p < 2; ++p) {      // nf pairs: (2p, 2p+1)
                u32 bh[4];
                ldsm_x4t(bh, w2h_b + bk + p * 32);
                mma16816(acc[2*p][0],   ah0, bh[0], bh[1]);
                mma16816(acc[2*p][1],   ah1, bh[0], bh[1]);
                mma16816(acc[2*p+1][0], ah0, bh[2], bh[3]);
                mma16816(acc[2*p+1][1], ah1, bh[2], bh[3]);
                mma16816(acc[2*p][0],   al0, bh[0], bh[1]);
                mma16816(acc[2*p][1],   al1, bh[0], bh[1]);
                mma16816(acc[2*p+1][0], al0, bh[2], bh[3]);
                mma16816(acc[2*p+1][1], al1, bh[2], bh[3]);
            }
        }

        // ======== epilogue: relu(+b2) dot W3, quad-reduce ========
        {
            float s[4] = {0.f, 0.f, 0.f, 0.f};
            #pragma unroll
            for (int nf = 0; nf < 4; ++nf) {
                const int c0 = cq * 32 + nf * 8 + tc;
                float2 bv = *(const float2*)(b2s + c0);
                float2 wv = *(const float2*)(W3s + c0);
                s[0] += fmaxf(acc[nf][0][0] + bv.x, 0.f) * wv.x
                      + fmaxf(acc[nf][0][1] + bv.y, 0.f) * wv.y;
                s[1] += fmaxf(acc[nf][0][2] + bv.x, 0.f) * wv.x
                      + fmaxf(acc[nf][0][3] + bv.y, 0.f) * wv.y;
                s[2] += fmaxf(acc[nf][1][0] + bv.x, 0.f) * wv.x
                      + fmaxf(acc[nf][1][1] + bv.y, 0.f) * wv.y;
                s[3] += fmaxf(acc[nf][1][2] + bv.x, 0.f) * wv.x
                      + fmaxf(acc[nf][1][3] + bv.y, 0.f) * wv.y;
            }
            #pragma unroll
            for (int d = 1; d <= 2; d <<= 1)
                #pragma unroll
                for (int q = 0; q < 4; ++q)
                    s[q] += __shfl_xor_sync(0xffffffffu, s[q], d);
            if ((lane & 3) == 0) {
                const int rows[4] = { m0 + tq, m0 + tq + 8, m0 + 16 + tq, m0 + 24 + tq };
                #pragma unroll
                for (int q = 0; q < 4; ++q)
                    if (i0 + rows[q] < nrows)
                        acc_e += s[q] + (cq == 0 ? b3r : 0.f);
            }
        }
    }

    // ---- warp reduce + atomic ----
    #pragma unroll
    for (int off = 16; off; off >>= 1)
        acc_e += __shfl_down_sync(0xffffffffu, acc_e, off);
    if (lane == 0) atomicAdd(&out[batch], acc_e);
}

extern "C" void kernel_launch(void* const* d_in, const int* in_sizes, int n_in,
                              void* d_out, int out_size) {
    const float* R   = (const float*)d_in[0];
    const int*   seq = (const int*)d_in[1];
    const float* emb = (const float*)d_in[2];
    const float* fl[6]; const float* ft[6]; const float* fp[6];
    for (int i = 0; i < 6; ++i) {
        fl[i] = (const float*)d_in[3 + i];
        ft[i] = (const float*)d_in[9 + i];
        fp[i] = (const float*)d_in[15 + i];
    }
    float* out = (float*)d_out;

    cudaFuncSetAttribute(mlp_energy_mma,
        cudaFuncAttributeMaxDynamicSharedMemorySize, SMEM_BYTES);

    build_tables<<<120, 256>>>(emb, fl[0], fl[1], ft[0], ft[1], fp[0], fp[1],
                               out, out_size);

    dim3 grid(3 * NBATCH * GPB);     // 3072 CTAs: [mlp | batch | group]
    mlp_energy_mma<<<grid, THREADS, SMEM_BYTES>>>(
        R, seq,
        fl[0], ft[0], fp[0],
        fl[2], ft[2], fp[2],
        fl[3], ft[3], fp[3],
        fl[4], ft[4], fp[4],
        fl[5], ft[5], fp[5],
        out);
}

// round 16
// speedup vs baseline: 1.1287x; 1.1287x over previous
#include <cuda_runtime.h>
#include <cuda_fp16.h>
#include <stdint.h>
#include <math.h>

#define THREADS  256
#define TILE     64
#define TPG      4      // tiles per CTA -> 256 rows
#define GPB      8      // CTAs per batch per mlp
#define LDIM     2048
#define NBATCH   128
#define RSTRIDE_B 272   // bytes per fp16 row (136 elems) -> conflict-free ldmatrix
#define RSTRIDE_W 68    // u32 words per row

typedef unsigned int u32;

// ---------------- PTX helpers ----------------
__device__ __forceinline__ u32 smem_u32(const void* p) {
    u32 a;
    asm("{ .reg .u64 t; cvta.to.shared.u64 t, %1; cvt.u32.u64 %0, t; }" : "=r"(a) : "l"(p));
    return a;
}
__device__ __forceinline__ void ldsm_x4(u32* r, u32 addr) {
    asm volatile("ldmatrix.sync.aligned.m8n8.x4.shared.b16 {%0,%1,%2,%3}, [%4];"
        : "=r"(r[0]), "=r"(r[1]), "=r"(r[2]), "=r"(r[3]) : "r"(addr));
}
__device__ __forceinline__ void ldsm_x4t(u32* r, u32 addr) {
    asm volatile("ldmatrix.sync.aligned.m8n8.x4.trans.shared.b16 {%0,%1,%2,%3}, [%4];"
        : "=r"(r[0]), "=r"(r[1]), "=r"(r[2]), "=r"(r[3]) : "r"(addr));
}
__device__ __forceinline__ void mma16816(float* d, const u32* a, u32 b0, u32 b1) {
    asm volatile("mma.sync.aligned.m16n8k16.row.col.f32.f16.f16.f32 "
        "{%0,%1,%2,%3}, {%4,%5,%6,%7}, {%8,%9}, {%0,%1,%2,%3};"
        : "+f"(d[0]), "+f"(d[1]), "+f"(d[2]), "+f"(d[3])
        : "r"(a[0]), "r"(a[1]), "r"(a[2]), "r"(a[3]), "r"(b0), "r"(b1));
}
// low half = fp16(a), high half = fp16(b); lw = fp16 residuals
__device__ __forceinline__ void split_pack_h(float a, float b, u32& hw, u32& lw) {
    u32 h;
    asm("cvt.rn.f16x2.f32 %0, %1, %2;" : "=r"(h) : "f"(b), "f"(a));
    __half2 hv = *reinterpret_cast<__half2*>(&h);
    float2 f = __half22float2(hv);
    float ar = a - f.x, br = b - f.y;
    u32 l;
    asm("cvt.rn.f16x2.f32 %0, %1, %2;" : "=r"(l) : "f"(br), "f"(ar));
    hw = h; lw = l;
}
__device__ __forceinline__ u32 pack_h(float a, float b) {
    u32 h;
    asm("cvt.rn.f16x2.f32 %0, %1, %2;" : "=r"(h) : "f"(b), "f"(a));
    return h;
}

// precomputed (emb x W1slot [+ b1 on slot 0]) tables: [mlp][slot*20+aa][col]
__device__ float g_tab[3 * 80 * 128];

__global__ void build_tables(const float* __restrict__ emb,
                             const float* __restrict__ W1l, const float* __restrict__ b1l,
                             const float* __restrict__ W1t, const float* __restrict__ b1t,
                             const float* __restrict__ W1p, const float* __restrict__ b1p,
                             float* __restrict__ out, int out_n) {
    int idx = blockIdx.x * blockDim.x + threadIdx.x;
    if (idx < out_n) out[idx] = 0.f;          // fold output zeroing here
    if (idx >= 3 * 80 * 128) return;
    int col  = idx & 127;
    int rest = idx >> 7;
    int mlp  = rest / 80;
    int s_aa = rest - mlp * 80;
    int slot = s_aa / 20;
    int aa   = s_aa - slot * 20;
    const float* W1 = (mlp == 0) ? W1l : (mlp == 1) ? W1t : W1p;
    const float* b1 = (mlp == 0) ? b1l : (mlp == 1) ? b1t : b1p;
    int geo  = (mlp == 2) ? 2 : 1;
    int nemb = mlp + 2;
    float s = 0.f;
    if (slot < nemb) {
        #pragma unroll
        for (int e = 0; e < 16; ++e)
            s += emb[aa * 16 + e] * W1[(size_t)(geo + slot * 16 + e) * 128 + col];
        if (slot == 0) s += b1[col];      // fold bias once
    }
    g_tab[idx] = s;
}

// smem layout (mlp-independent)
#define OFF_W2H  0
#define OFF_XH   (OFF_W2H + 128 * RSTRIDE_B)
#define OFF_XL   (OFF_XH + TILE * RSTRIDE_B)
#define OFF_BIAS (OFF_XL + TILE * RSTRIDE_B)
#define SMEM_BYTES (OFF_BIAS + 2 * 512)        // ~69 KB -> 3 CTAs/SM

// ================= templated per-CTA body (compile-time NEMB) =================
template<int NEMB>
__device__ __forceinline__ void mlp_body(
    int blk, char* smem,
    const float* __restrict__ R, const int* __restrict__ seq,
    const float* __restrict__ gW1,
    const float* __restrict__ gW2, const float* __restrict__ gb2,
    const float* __restrict__ gW3, const float* __restrict__ gb3,
    float* __restrict__ out)
{
    constexpr int GEO   = (NEMB == 4) ? 2 : 1;
    constexpr int NROWS = LDIM - NEMB + 1;
    constexpr int MLP   = NEMB - 2;

    float* b2s  = (float*)(smem + OFF_BIAS);
    float* W3s  = b2s + 128;

    const int tid  = threadIdx.x;
    const int wid  = tid >> 5;
    const int lane = tid & 31;
    const int batch = blk / GPB;
    const int group = blk % GPB;

    // ---- stage biases / W2 fp16 (K-major [K][128]) ----
    if (tid < 128) { b2s[tid] = gb2[tid]; W3s[tid] = gW3[tid]; }
    {
        u32* wh = (u32*)(smem + OFF_W2H);
        for (int idx = tid; idx < 128 * 64; idx += THREADS) {
            int k = idx >> 6, np = idx & 63;
            int n = 2 * np;
            float w0 = gW2[(size_t)k * 128 + n];
            float w1 = gW2[(size_t)k * 128 + n + 1];
            wh[k * RSTRIDE_W + np] = pack_h(w0, w1);
        }
    }
    __syncthreads();

    const float b3r = gb3[0];
    const float* Rb   = R   + (size_t)batch * LDIM * 3;
    const int*   seqb = seq + (size_t)batch * LDIM;
    const float4* tab4 = (const float4*)(g_tab + MLP * 10240);  // L2-hot table
    const int row_base = group * (TILE * TPG);

    // geo weight rows of W1 kept in registers (uniform per lane, L2-hot)
    float4 wg0 = *(const float4*)(gW1 + lane * 4);
    float4 wg1 = make_float4(0.f, 0.f, 0.f, 0.f);
    if (GEO == 2) wg1 = *(const float4*)(gW1 + 128 + lane * 4);

    const u32 xh_b  = smem_u32(smem + OFF_XH);
    const u32 xl_b  = smem_u32(smem + OFF_XL);
    const u32 w2h_b = smem_u32(smem + OFF_W2H);

    // gemm mapping: 8 warps = 2 row-groups (32 rows) x 4 N-quarters (32 cols)
    const int rg = wid >> 2;
    const int cq = wid & 3;
    const int m0 = rg * 32;
    const u32 aoff0 = (u32)(m0 + (lane & 15)) * RSTRIDE_B + (u32)(lane >> 4) * 16;
    const u32 aoff1 = aoff0 + 16 * RSTRIDE_B;
    const int l8 = lane & 7, lg = lane >> 3;
    const u32 boff4 = (u32)(l8 + (lg & 1) * 8) * RSTRIDE_B
                    + (u32)(lg >> 1) * 16 + (u32)cq * 64;

    u32* hh = (u32*)(smem + OFF_XH);
    u32* hl = (u32*)(smem + OFF_XL);
    const int tq = lane >> 2;
    const int tc = 2 * (lane & 3);

    const int wrow0 = wid * 8;    // build: warp owns rows wrow0..wrow0+7

    float acc_e = 0.f;

    for (int tt = 0; tt < TPG; ++tt) {
        const int i0 = row_base + tt * TILE;
        __syncthreads();   // previous tile's gemm reads done

        // ======== build h1 (warp-per-row, broadcast table LDGs) ========
        {
            // lanes 0..7: geometry for row i0+wrow0+lane
            float geo0 = 0.f, geo1 = 0.f;
            {
                const int i = i0 + wrow0 + (lane & 7);
                if (lane < 8 && i < NROWS) {
                    float p0x = Rb[i*3+0],     p0y = Rb[i*3+1],     p0z = Rb[i*3+2];
                    float p1x = Rb[(i+1)*3+0], p1y = Rb[(i+1)*3+1], p1z = Rb[(i+1)*3+2];
                    float d0x = p1x - p0x, d0y = p1y - p0y, d0z = p1z - p0z;
                    if (NEMB == 2) {
                        geo0 = sqrtf(d0x*d0x + d0y*d0y + d0z*d0z);
                    } else if (NEMB == 3) {
                        float p2x = Rb[(i+2)*3+0], p2y = Rb[(i+2)*3+1], p2z = Rb[(i+2)*3+2];
                        float d1x = p2x - p1x, d1y = p2y - p1y, d1z = p2z - p1z;
                        float dot01 = d0x*d1x + d0y*d1y + d0z*d1z;
                        float n0 = d0x*d0x + d0y*d0y + d0z*d0z;
                        float n1 = d1x*d1x + d1y*d1y + d1z*d1z;
                        float c  = -dot01 / (sqrtf(n0) * sqrtf(n1));
                        geo0 = fminf(1.f, fmaxf(-1.f, c));
                    } else {
                        float p2x = Rb[(i+2)*3+0], p2y = Rb[(i+2)*3+1], p2z = Rb[(i+2)*3+2];
                        float p3x = Rb[(i+3)*3+0], p3y = Rb[(i+3)*3+1], p3z = Rb[(i+3)*3+2];
                        float d1x = p2x - p1x, d1y = p2y - p1y, d1z = p2z - p1z;
                        float d2x = p3x - p2x, d2y = p3y - p2y, d2z = p3z - p2z;
                        float n1x = d0y*d1z - d0z*d1y;
                        float n1y = d0z*d1x - d0x*d1z;
                        float n1z = d0x*d1y - d0y*d1x;
                        float n2x = d1y*d2z - d1z*d2y;
                        float n2y = d1z*d2x - d1x*d2z;
                        float n2z = d1x*d2y - d1y*d2x;
                        float inv = rsqrtf(d1x*d1x + d1y*d1y + d1z*d1z);
                        float ux = d1x*inv, uy = d1y*inv, uz = d1z*inv;
                        float m1x = n1y*uz - n1z*uy;
                        float m1y = n1z*ux - n1x*uz;
                        float m1z = n1x*uy - n1y*ux;
                        float yv = m1x*n2x + m1y*n2y + m1z*n2z;
                        float xv = n1x*n2x + n1y*n2y + n1z*n2z;
                        float rinv = rsqrtf(xv*xv + yv*yv);
                        geo0 = yv * rinv;
                        geo1 = xv * rinv;
                    }
                }
            }
            // seq values for rows wrow0..wrow0+7 (+NEMB-1)
            int sval;
            {
                int sidx = i0 + wrow0 + lane;
                sval = (sidx < LDIM) ? seqb[sidx] : 0;
            }

            #pragma unroll 4
            for (int r = 0; r < 8; ++r) {
                float g0 = __shfl_sync(0xffffffffu, geo0, r);
                float g1 = __shfl_sync(0xffffffffu, geo1, r);
                float4 s = make_float4(0.f, 0.f, 0.f, 0.f);
                #pragma unroll
                for (int v = 0; v < NEMB; ++v) {
                    int aa = __shfl_sync(0xffffffffu, sval, r + v);
                    float4 t = tab4[(v * 20 + aa) * 32 + lane];   // coalesced 512B row
                    s.x += t.x; s.y += t.y; s.z += t.z; s.w += t.w;
                }
                s.x += g0 * wg0.x; s.y += g0 * wg0.y; s.z += g0 * wg0.z; s.w += g0 * wg0.w;
                if (GEO == 2) {
                    s.x += g1 * wg1.x; s.y += g1 * wg1.y; s.z += g1 * wg1.z; s.w += g1 * wg1.w;
                }
                u32 hw0, lw0, hw1, lw1;
                split_pack_h(fmaxf(s.x, 0.f), fmaxf(s.y, 0.f), hw0, lw0);
                split_pack_h(fmaxf(s.z, 0.f), fmaxf(s.w, 0.f), hw1, lw1);
                const int p = (wrow0 + r) * RSTRIDE_W + 2 * lane;
                *(uint2*)(hh + p) = make_uint2(hw0, hw1);
                *(uint2*)(hl + p) = make_uint2(lw0, lw1);
            }
        }
        __syncthreads();

        // ======== layer-2 GEMM: M=32 rows x N=32 cols per warp, 2-term fp16 ========
        float acc[4][2][4];
        #pragma unroll
        for (int nf = 0; nf < 4; ++nf)
            #pragma unroll
            for (int mf = 0; mf < 2; ++mf)
                #pragma unroll
                for (int q = 0; q < 4; ++q) acc[nf][mf][q] = 0.f;

        #pragma unroll 1
        for (int k = 0; k < 8; ++k) {
            u32 ah0[4], ah1[4], al0[4], al1[4];
            ldsm_x4(ah0, xh_b + aoff0 + k * 32);
            ldsm_x4(ah1, xh_b + aoff1 + k * 32);
            ldsm_x4(al0, xl_b + aoff0 + k * 32);
            ldsm_x4(al1, xl_b + aoff1 + k * 32);
            u32 bk = boff4 + (u32)k * 16 * RSTRIDE_B;
            #pragma unroll
            for (int p = 0; p < 2; ++p) {      // nf pairs: (2p, 2p+1)
                u32 bh[4];
                ldsm_x4t(bh, w2h_b + bk + p * 32);
                mma16816(acc[2*p][0],   ah0, bh[0], bh[1]);
                mma16816(acc[2*p][1],   ah1, bh[0], bh[1]);
                mma16816(acc[2*p+1][0], ah0, bh[2], bh[3]);
                mma16816(acc[2*p+1][1], ah1, bh[2], bh[3]);
                mma16816(acc[2*p][0],   al0, bh[0], bh[1]);
                mma16816(acc[2*p][1],   al1, bh[0], bh[1]);
                mma16816(acc[2*p+1][0], al0, bh[2], bh[3]);
                mma16816(acc[2*p+1][1], al1, bh[2], bh[3]);
            }
        }

        // ======== epilogue: relu(+b2) dot W3, quad-reduce ========
        {
            float s[4] = {0.f, 0.f, 0.f, 0.f};
            #pragma unroll
            for (int nf = 0; nf < 4; ++nf) {
                const int c0 = cq * 32 + nf * 8 + tc;
                float2 bv = *(const float2*)(b2s + c0);
                float2 wv = *(const float2*)(W3s + c0);
                s[0] += fmaxf(acc[nf][0][0] + bv.x, 0.f) * wv.x
                      + fmaxf(acc[nf][0][1] + bv.y, 0.f) * wv.y;
                s[1] += fmaxf(acc[nf][0][2] + bv.x, 0.f) * wv.x
                      + fmaxf(acc[nf][0][3] + bv.y, 0.f) * wv.y;
                s[2] += fmaxf(acc[nf][1][0] + bv.x, 0.f) * wv.x
                      + fmaxf(acc[nf][1][1] + bv.y, 0.f) * wv.y;
                s[3] += fmaxf(acc[nf][1][2] + bv.x, 0.f) * wv.x
                      + fmaxf(acc[nf][1][3] + bv.y, 0.f) * wv.y;
            }
            #pragma unroll
            for (int d = 1; d <= 2; d <<= 1)
                #pragma unroll
                for (int q = 0; q < 4; ++q)
                    s[q] += __shfl_xor_sync(0xffffffffu, s[q], d);
            if ((lane & 3) == 0) {
                const int rows[4] = { m0 + tq, m0 + tq + 8, m0 + 16 + tq, m0 + 24 + tq };
                #pragma unroll
                for (int q = 0; q < 4; ++q)
                    if (i0 + rows[q] < NROWS)
                        acc_e += s[q] + (cq == 0 ? b3r : 0.f);
            }
        }
    }

    // ---- warp reduce + atomic ----
    #pragma unroll
    for (int off = 16; off; off >>= 1)
        acc_e += __shfl_down_sync(0xffffffffu, acc_e, off);
    if (lane == 0) atomicAdd(&out[batch], acc_e);
}

__global__ __launch_bounds__(THREADS, 3)
void mlp_energy_mma(const float* __restrict__ R,
                    const int*   __restrict__ seq,
                    const float* __restrict__ W1a, const float* __restrict__ W1b, const float* __restrict__ W1c,
                    const float* __restrict__ W2a, const float* __restrict__ W2b, const float* __restrict__ W2c,
                    const float* __restrict__ b2a, const float* __restrict__ b2b, const float* __restrict__ b2c,
                    const float* __restrict__ W3a, const float* __restrict__ W3b, const float* __restrict__ W3c,
                    const float* __restrict__ b3a, const float* __restrict__ b3b, const float* __restrict__ b3c,
                    float* __restrict__ out)
{
    extern __shared__ char smem[];
    const int mlp = blockIdx.x >> 10;          // 0..2
    const int blk = blockIdx.x & 1023;
    if (mlp == 0)
        mlp_body<2>(blk, smem, R, seq, W1a, W2a, b2a, W3a, b3a, out);
    else if (mlp == 1)
        mlp_body<3>(blk, smem, R, seq, W1b, W2b, b2b, W3b, b3b, out);
    else
        mlp_body<4>(blk, smem, R, seq, W1c, W2c, b2c, W3c, b3c, out);
}

extern "C" void kernel_launch(void* const* d_in, const int* in_sizes, int n_in,
                              void* d_out, int out_size) {
    const float* R   = (const float*)d_in[0];
    const int*   seq = (const int*)d_in[1];
    const float* emb = (const float*)d_in[2];
    const float* fl[6]; const float* ft[6]; const float* fp[6];
    for (int i = 0; i < 6; ++i) {
        fl[i] = (const float*)d_in[3 + i];
        ft[i] = (const float*)d_in[9 + i];
        fp[i] = (const float*)d_in[15 + i];
    }
    float* out = (float*)d_out;

    cudaFuncSetAttribute(mlp_energy_mma,
        cudaFuncAttributeMaxDynamicSharedMemorySize, SMEM_BYTES);

    build_tables<<<120, 256>>>(emb, fl[0], fl[1], ft[0], ft[1], fp[0], fp[1],
                               out, out_size);

    dim3 grid(3 * NBATCH * GPB);     // 3072 CTAs: [mlp | batch | group]
    mlp_energy_mma<<<grid, THREADS, SMEM_BYTES>>>(
        R, seq,
        fl[0], ft[0], fp[0],
        fl[2], ft[2], fp[2],
        fl[3], ft[3], fp[3],
        fl[4], ft[4], fp[4],
        fl[5], ft[5], fp[5],
        out);
}

// round 17
// speedup vs baseline: 1.2801x; 1.1341x over previous
#include <cuda_runtime.h>
#include <cuda_fp16.h>
#include <stdint.h>
#include <math.h>

#define THREADS  256
#define TILE     64
#define TPG      4      // tiles per CTA -> 256 rows
#define GPB      8      // CTAs per batch per mlp
#define LDIM     2048
#define NBATCH   128
#define RSTRIDE_B 272   // bytes per fp16 row (136 elems) -> conflict-free ldmatrix
#define RSTRIDE_W 68    // u32 words per row

typedef unsigned int u32;

// ---------------- PTX helpers ----------------
__device__ __forceinline__ u32 smem_u32(const void* p) {
    u32 a;
    asm("{ .reg .u64 t; cvta.to.shared.u64 t, %1; cvt.u32.u64 %0, t; }" : "=r"(a) : "l"(p));
    return a;
}
__device__ __forceinline__ void ldsm_x4(u32* r, u32 addr) {
    asm volatile("ldmatrix.sync.aligned.m8n8.x4.shared.b16 {%0,%1,%2,%3}, [%4];"
        : "=r"(r[0]), "=r"(r[1]), "=r"(r[2]), "=r"(r[3]) : "r"(addr));
}
__device__ __forceinline__ void ldsm_x4t(u32* r, u32 addr) {
    asm volatile("ldmatrix.sync.aligned.m8n8.x4.trans.shared.b16 {%0,%1,%2,%3}, [%4];"
        : "=r"(r[0]), "=r"(r[1]), "=r"(r[2]), "=r"(r[3]) : "r"(addr));
}
__device__ __forceinline__ void mma16816(float* d, const u32* a, u32 b0, u32 b1) {
    asm volatile("mma.sync.aligned.m16n8k16.row.col.f32.f16.f16.f32 "
        "{%0,%1,%2,%3}, {%4,%5,%6,%7}, {%8,%9}, {%0,%1,%2,%3};"
        : "+f"(d[0]), "+f"(d[1]), "+f"(d[2]), "+f"(d[3])
        : "r"(a[0]), "r"(a[1]), "r"(a[2]), "r"(a[3]), "r"(b0), "r"(b1));
}
// low half = fp16(a), high half = fp16(b); lw = fp16 residuals
__device__ __forceinline__ void split_pack_h(float a, float b, u32& hw, u32& lw) {
    u32 h;
    asm("cvt.rn.f16x2.f32 %0, %1, %2;" : "=r"(h) : "f"(b), "f"(a));
    __half2 hv = *reinterpret_cast<__half2*>(&h);
    float2 f = __half22float2(hv);
    float ar = a - f.x, br = b - f.y;
    u32 l;
    asm("cvt.rn.f16x2.f32 %0, %1, %2;" : "=r"(l) : "f"(br), "f"(ar));
    hw = h; lw = l;
}
__device__ __forceinline__ u32 pack_h(float a, float b) {
    u32 h;
    asm("cvt.rn.f16x2.f32 %0, %1, %2;" : "=r"(h) : "f"(b), "f"(a));
    return h;
}

// precomputed (emb x W1slot [+ b1 on slot 0]) tables: [mlp][slot*20+aa][col]
__device__ float g_tab[3 * 80 * 128];
// pairwise tables: buf0=mlp0(s0+s1), buf1=mlp1(s0+s1), buf2=mlp2(s0+s1), buf3=mlp2(s2+s3)
__device__ float g_pair[4 * 400 * 128];
// pre-packed fp16 W2 in RSTRIDE layout: [mlp][k][RSTRIDE_W]
__device__ u32 g_w2p[3 * 128 * RSTRIDE_W];

__global__ void build_tables(const float* __restrict__ emb,
                             const float* __restrict__ W1l, const float* __restrict__ b1l,
                             const float* __restrict__ W1t, const float* __restrict__ b1t,
                             const float* __restrict__ W1p, const float* __restrict__ b1p,
                             float* __restrict__ out, int out_n) {
    int idx = blockIdx.x * blockDim.x + threadIdx.x;
    if (idx < out_n) out[idx] = 0.f;          // fold output zeroing here
    if (idx >= 3 * 80 * 128) return;
    int col  = idx & 127;
    int rest = idx >> 7;
    int mlp  = rest / 80;
    int s_aa = rest - mlp * 80;
    int slot = s_aa / 20;
    int aa   = s_aa - slot * 20;
    const float* W1 = (mlp == 0) ? W1l : (mlp == 1) ? W1t : W1p;
    const float* b1 = (mlp == 0) ? b1l : (mlp == 1) ? b1t : b1p;
    int geo  = (mlp == 2) ? 2 : 1;
    int nemb = mlp + 2;
    float s = 0.f;
    if (slot < nemb) {
        #pragma unroll
        for (int e = 0; e < 16; ++e)
            s += emb[aa * 16 + e] * W1[(size_t)(geo + slot * 16 + e) * 128 + col];
        if (slot == 0) s += b1[col];      // fold bias once
    }
    g_tab[idx] = s;
}

// second pre-kernel: pair tables (from g_tab) + fp16 W2 pre-pack
__global__ void build_pairs(const float* __restrict__ W2a,
                            const float* __restrict__ W2b,
                            const float* __restrict__ W2c) {
    int idx = blockIdx.x * blockDim.x + threadIdx.x;
    if (idx < 4 * 400 * 128) {
        int col  = idx & 127;
        int rest = idx >> 7;          // 0..1599
        int buf  = rest / 400;
        int ab   = rest - buf * 400;
        int a = ab / 20, b = ab - (ab / 20) * 20;
        int mlp = (buf <= 1) ? buf : 2;
        int s0  = (buf == 3) ? 2 : 0;
        const float* base = g_tab + mlp * 10240;
        g_pair[idx] = base[(s0 * 20 + a) * 128 + col]
                    + base[((s0 + 1) * 20 + b) * 128 + col];
        return;
    }
    int j = idx - 4 * 400 * 128;
    if (j < 3 * 128 * 64) {
        int mlp = j / 8192;
        int r   = j - mlp * 8192;
        int k = r >> 6, np = r & 63;
        const float* W2 = (mlp == 0) ? W2a : (mlp == 1) ? W2b : W2c;
        float w0 = W2[(size_t)k * 128 + 2 * np];
        float w1 = W2[(size_t)k * 128 + 2 * np + 1];
        g_w2p[mlp * 128 * RSTRIDE_W + k * RSTRIDE_W + np] = pack_h(w0, w1);
    }
}

// smem layout (mlp-independent)
#define OFF_W2H  0
#define OFF_XH   (OFF_W2H + 128 * RSTRIDE_B)
#define OFF_XL   (OFF_XH + TILE * RSTRIDE_B)
#define OFF_BIAS (OFF_XL + TILE * RSTRIDE_B)
#define SMEM_BYTES (OFF_BIAS + 2 * 512)        // ~69 KB -> 3 CTAs/SM

// ================= templated per-CTA body (compile-time NEMB) =================
template<int NEMB>
__device__ __forceinline__ void mlp_body(
    int blk, char* smem,
    const float* __restrict__ R, const int* __restrict__ seq,
    const float* __restrict__ gW1,
    const float* __restrict__ gb2,
    const float* __restrict__ gW3, const float* __restrict__ gb3,
    float* __restrict__ out)
{
    constexpr int GEO   = (NEMB == 4) ? 2 : 1;
    constexpr int NROWS = LDIM - NEMB + 1;
    constexpr int MLP   = NEMB - 2;

    float* b2s  = (float*)(smem + OFF_BIAS);
    float* W3s  = b2s + 128;

    const int tid  = threadIdx.x;
    const int wid  = tid >> 5;
    const int lane = tid & 31;
    const int batch = blk / GPB;
    const int group = blk % GPB;

    // ---- stage biases / copy pre-packed W2 ----
    if (tid < 128) { b2s[tid] = gb2[tid]; W3s[tid] = gW3[tid]; }
    {
        const uint4* src = (const uint4*)(g_w2p + MLP * 128 * RSTRIDE_W);
        uint4* dst = (uint4*)(smem + OFF_W2H);
        #pragma unroll
        for (int i = 0; i < 2176 / THREADS + 1; ++i) {
            int p = tid + i * THREADS;
            if (p < 2176) dst[p] = src[p];
        }
    }
    __syncthreads();

    const float b3r = gb3[0];
    const float* Rb   = R   + (size_t)batch * LDIM * 3;
    const int*   seqb = seq + (size_t)batch * LDIM;
    const float4* tab4  = (const float4*)(g_tab + MLP * 10240);
    const float4* pair0 = (const float4*)(g_pair + ((MLP == 2) ? 2 : MLP) * 51200);
    const float4* pair1 = (const float4*)(g_pair + 3 * 51200);
    const int row_base = group * (TILE * TPG);

    // geo weight rows of W1 kept in registers (uniform per lane, L2-hot)
    float4 wg0 = *(const float4*)(gW1 + lane * 4);
    float4 wg1 = make_float4(0.f, 0.f, 0.f, 0.f);
    if (GEO == 2) wg1 = *(const float4*)(gW1 + 128 + lane * 4);

    const u32 xh_b  = smem_u32(smem + OFF_XH);
    const u32 xl_b  = smem_u32(smem + OFF_XL);
    const u32 w2h_b = smem_u32(smem + OFF_W2H);

    // gemm mapping: 8 warps = 2 row-groups (32 rows) x 4 N-quarters (32 cols)
    const int rg = wid >> 2;
    const int cq = wid & 3;
    const int m0 = rg * 32;
    const u32 aoff0 = (u32)(m0 + (lane & 15)) * RSTRIDE_B + (u32)(lane >> 4) * 16;
    const u32 aoff1 = aoff0 + 16 * RSTRIDE_B;
    const int l8 = lane & 7, lg = lane >> 3;
    const u32 boff4 = (u32)(l8 + (lg & 1) * 8) * RSTRIDE_B
                    + (u32)(lg >> 1) * 16 + (u32)cq * 64;

    u32* hh = (u32*)(smem + OFF_XH);
    u32* hl = (u32*)(smem + OFF_XL);
    const int tq = lane >> 2;
    const int tc = 2 * (lane & 3);

    const int wrow0 = wid * 8;    // build: warp owns rows wrow0..wrow0+7

    float acc_e = 0.f;

    for (int tt = 0; tt < TPG; ++tt) {
        const int i0 = row_base + tt * TILE;
        __syncthreads();   // previous tile's gemm reads done

        // ======== build h1 (warp-per-row, broadcast pair-table LDGs) ========
        {
            // lanes 0..7: geometry for row i0+wrow0+lane
            float geo0 = 0.f, geo1 = 0.f;
            {
                const int i = i0 + wrow0 + (lane & 7);
                if (lane < 8 && i < NROWS) {
                    float p0x = Rb[i*3+0],     p0y = Rb[i*3+1],     p0z = Rb[i*3+2];
                    float p1x = Rb[(i+1)*3+0], p1y = Rb[(i+1)*3+1], p1z = Rb[(i+1)*3+2];
                    float d0x = p1x - p0x, d0y = p1y - p0y, d0z = p1z - p0z;
                    if (NEMB == 2) {
                        geo0 = sqrtf(d0x*d0x + d0y*d0y + d0z*d0z);
                    } else if (NEMB == 3) {
                        float p2x = Rb[(i+2)*3+0], p2y = Rb[(i+2)*3+1], p2z = Rb[(i+2)*3+2];
                        float d1x = p2x - p1x, d1y = p2y - p1y, d1z = p2z - p1z;
                        float dot01 = d0x*d1x + d0y*d1y + d0z*d1z;
                        float n0 = d0x*d0x + d0y*d0y + d0z*d0z;
                        float n1 = d1x*d1x + d1y*d1y + d1z*d1z;
                        float c  = -dot01 / (sqrtf(n0) * sqrtf(n1));
                        geo0 = fminf(1.f, fmaxf(-1.f, c));
                    } else {
                        float p2x = Rb[(i+2)*3+0], p2y = Rb[(i+2)*3+1], p2z = Rb[(i+2)*3+2];
                        float p3x = Rb[(i+3)*3+0], p3y = Rb[(i+3)*3+1], p3z = Rb[(i+3)*3+2];
                        float d1x = p2x - p1x, d1y = p2y - p1y, d1z = p2z - p1z;
                        float d2x = p3x - p2x, d2y = p3y - p2y, d2z = p3z - p2z;
                        float n1x = d0y*d1z - d0z*d1y;
                        float n1y = d0z*d1x - d0x*d1z;
                        float n1z = d0x*d1y - d0y*d1x;
                        float n2x = d1y*d2z - d1z*d2y;
                        float n2y = d1z*d2x - d1x*d2z;
                        float n2z = d1x*d2y - d1y*d2x;
                        float inv = rsqrtf(d1x*d1x + d1y*d1y + d1z*d1z);
                        float ux = d1x*inv, uy = d1y*inv, uz = d1z*inv;
                        float m1x = n1y*uz - n1z*uy;
                        float m1y = n1z*ux - n1x*uz;
                        float m1z = n1x*uy - n1y*ux;
                        float yv = m1x*n2x + m1y*n2y + m1z*n2z;
                        float xv = n1x*n2x + n1y*n2y + n1z*n2z;
                        float rinv = rsqrtf(xv*xv + yv*yv);
                        geo0 = yv * rinv;
                        geo1 = xv * rinv;
                    }
                }
            }
            // seq values for rows wrow0..wrow0+7 (+NEMB-1)
            int sval;
            {
                int sidx = i0 + wrow0 + lane;
                sval = (sidx < LDIM) ? seqb[sidx] : 0;
            }

            #pragma unroll 4
            for (int r = 0; r < 8; ++r) {
                float g0 = __shfl_sync(0xffffffffu, geo0, r);
                float g1 = __shfl_sync(0xffffffffu, geo1, r);
                int a0 = __shfl_sync(0xffffffffu, sval, r);
                int a1 = __shfl_sync(0xffffffffu, sval, r + 1);
                float4 s;
                if (NEMB == 2) {
                    s = pair0[(a0 * 20 + a1) * 32 + lane];
                } else if (NEMB == 3) {
                    int a2 = __shfl_sync(0xffffffffu, sval, r + 2);
                    float4 p = pair0[(a0 * 20 + a1) * 32 + lane];
                    float4 t = tab4[(40 + a2) * 32 + lane];
                    s = make_float4(p.x + t.x, p.y + t.y, p.z + t.z, p.w + t.w);
                } else {
                    int a2 = __shfl_sync(0xffffffffu, sval, r + 2);
                    int a3 = __shfl_sync(0xffffffffu, sval, r + 3);
                    float4 p = pair0[(a0 * 20 + a1) * 32 + lane];
                    float4 q = pair1[(a2 * 20 + a3) * 32 + lane];
                    s = make_float4(p.x + q.x, p.y + q.y, p.z + q.z, p.w + q.w);
                }
                s.x += g0 * wg0.x; s.y += g0 * wg0.y; s.z += g0 * wg0.z; s.w += g0 * wg0.w;
                if (GEO == 2) {
                    s.x += g1 * wg1.x; s.y += g1 * wg1.y; s.z += g1 * wg1.z; s.w += g1 * wg1.w;
                }
                u32 hw0, lw0, hw1, lw1;
                split_pack_h(fmaxf(s.x, 0.f), fmaxf(s.y, 0.f), hw0, lw0);
                split_pack_h(fmaxf(s.z, 0.f), fmaxf(s.w, 0.f), hw1, lw1);
                const int p = (wrow0 + r) * RSTRIDE_W + 2 * lane;
                *(uint2*)(hh + p) = make_uint2(hw0, hw1);
                *(uint2*)(hl + p) = make_uint2(lw0, lw1);
            }
        }
        __syncthreads();

        // ======== layer-2 GEMM: M=32 rows x N=32 cols per warp, 2-term fp16 ========
        float acc[4][2][4];
        #pragma unroll
        for (int nf = 0; nf < 4; ++nf)
            #pragma unroll
            for (int mf = 0; mf < 2; ++mf)
                #pragma unroll
                for (int q = 0; q < 4; ++q) acc[nf][mf][q] = 0.f;

        #pragma unroll 1
        for (int k = 0; k < 8; ++k) {
            u32 ah0[4], ah1[4], al0[4], al1[4];
            ldsm_x4(ah0, xh_b + aoff0 + k * 32);
            ldsm_x4(ah1, xh_b + aoff1 + k * 32);
            ldsm_x4(al0, xl_b + aoff0 + k * 32);
            ldsm_x4(al1, xl_b + aoff1 + k * 32);
            u32 bk = boff4 + (u32)k * 16 * RSTRIDE_B;
            #pragma unroll
            for (int p = 0; p < 2; ++p) {      // nf pairs: (2p, 2p+1)
                u32 bh[4];
                ldsm_x4t(bh, w2h_b + bk + p * 32);
                mma16816(acc[2*p][0],   ah0, bh[0], bh[1]);
                mma16816(acc[2*p][1],   ah1, bh[0], bh[1]);
                mma16816(acc[2*p+1][0], ah0, bh[2], bh[3]);
                mma16816(acc[2*p+1][1], ah1, bh[2], bh[3]);
                mma16816(acc[2*p][0],   al0, bh[0], bh[1]);
                mma16816(acc[2*p][1],   al1, bh[0], bh[1]);
                mma16816(acc[2*p+1][0], al0, bh[2], bh[3]);
                mma16816(acc[2*p+1][1], al1, bh[2], bh[3]);
            }
        }

        // ======== epilogue: relu(+b2) dot W3, quad-reduce ========
        {
            float s[4] = {0.f, 0.f, 0.f, 0.f};
            #pragma unroll
            for (int nf = 0; nf < 4; ++nf) {
                const int c0 = cq * 32 + nf * 8 + tc;
                float2 bv = *(const float2*)(b2s + c0);
                float2 wv = *(const float2*)(W3s + c0);
                s[0] += fmaxf(acc[nf][0][0] + bv.x, 0.f) * wv.x
                      + fmaxf(acc[nf][0][1] + bv.y, 0.f) * wv.y;
                s[1] += fmaxf(acc[nf][0][2] + bv.x, 0.f) * wv.x
                      + fmaxf(acc[nf][0][3] + bv.y, 0.f) * wv.y;
                s[2] += fmaxf(acc[nf][1][0] + bv.x, 0.f) * wv.x
                      + fmaxf(acc[nf][1][1] + bv.y, 0.f) * wv.y;
                s[3] += fmaxf(acc[nf][1][2] + bv.x, 0.f) * wv.x
                      + fmaxf(acc[nf][1][3] + bv.y, 0.f) * wv.y;
            }
            #pragma unroll
            for (int d = 1; d <= 2; d <<= 1)
                #pragma unroll
                for (int q = 0; q < 4; ++q)
                    s[q] += __shfl_xor_sync(0xffffffffu, s[q], d);
            if ((lane & 3) == 0) {
                const int rows[4] = { m0 + tq, m0 + tq + 8, m0 + 16 + tq, m0 + 24 + tq };
                #pragma unroll
                for (int q = 0; q < 4; ++q)
                    if (i0 + rows[q] < NROWS)
                        acc_e += s[q] + (cq == 0 ? b3r : 0.f);
            }
        }
    }

    // ---- warp reduce + atomic ----
    #pragma unroll
    for (int off = 16; off; off >>= 1)
        acc_e += __shfl_down_sync(0xffffffffu, acc_e, off);
    if (lane == 0) atomicAdd(&out[batch], acc_e);
}

__global__ __launch_bounds__(THREADS, 3)
void mlp_energy_mma(const float* __restrict__ R,
                    const int*   __restrict__ seq,
                    const float* __restrict__ W1a, const float* __restrict__ W1b, const float* __restrict__ W1c,
                    const float* __restrict__ b2a, const float* __restrict__ b2b, const float* __restrict__ b2c,
                    const float* __restrict__ W3a, const float* __restrict__ W3b, const float* __restrict__ W3c,
                    const float* __restrict__ b3a, const float* __restrict__ b3b, const float* __restrict__ b3c,
                    float* __restrict__ out)
{
    extern __shared__ char smem[];
    const int mlp = blockIdx.x >> 10;          // 0..2
    const int blk = blockIdx.x & 1023;
    if (mlp == 0)
        mlp_body<2>(blk, smem, R, seq, W1a, b2a, W3a, b3a, out);
    else if (mlp == 1)
        mlp_body<3>(blk, smem, R, seq, W1b, b2b, W3b, b3b, out);
    else
        mlp_body<4>(blk, smem, R, seq, W1c, b2c, W3c, b3c, out);
}

extern "C" void kernel_launch(void* const* d_in, const int* in_sizes, int n_in,
                              void* d_out, int out_size) {
    const float* R   = (const float*)d_in[0];
    const int*   seq = (const int*)d_in[1];
    const float* emb = (const float*)d_in[2];
    const float* fl[6]; const float* ft[6]; const float* fp[6];
    for (int i = 0; i < 6; ++i) {
        fl[i] = (const float*)d_in[3 + i];
        ft[i] = (const float*)d_in[9 + i];
        fp[i] = (const float*)d_in[15 + i];
    }
    float* out = (float*)d_out;

    cudaFuncSetAttribute(mlp_energy_mma,
        cudaFuncAttributeMaxDynamicSharedMemorySize, SMEM_BYTES);

    build_tables<<<120, 256>>>(emb, fl[0], fl[1], ft[0], ft[1], fp[0], fp[1],
                               out, out_size);
    build_pairs<<<897, 256>>>(fl[2], ft[2], fp[2]);

    dim3 grid(3 * NBATCH * GPB);     // 3072 CTAs: [mlp | batch | group]
    mlp_energy_mma<<<grid, THREADS, SMEM_BYTES>>>(
        R, seq,
        fl[0], ft[0], fp[0],
        fl[3], ft[3], fp[3],
        fl[4], ft[4], fp[4],
        fl[5], ft[5], fp[5],
        out);
}